// round 12
// baseline (speedup 1.0000x reference)
#include <cuda_runtime.h>
#include <cuda_fp16.h>
#include <cstdint>
#include <cstddef>

// VeRA: y = x @ W^T + ((x @ A^T) * d) @ B^T + b    (all f32 I/O)
// fp16 mma.sync m16n8k16 (f32 acc). BK=128 double-subtile chunks, 2 stages,
// 256x128 CTA tile (warp 64x64), xa via split-K x2 + combine.

#define M_TOT 8192
#define N_TOT 4096
#define K_TOT 4096
#define RNK   256

#define BM 256
#define BN 128
#define BK 128                // halves per chunk (two 64-half sub-tiles)
#define STAGES 2
#define GROUP_M 8

#define A_SUB (BM * 128)                       // bytes per A sub-tile
#define B_SUB (BN * 128)
#define STAGE_BYTES (2 * (A_SUB + B_SUB))      // 98304
#define SMEM_TOTAL (STAGES * STAGE_BYTES)      // 196608

// ---------- static scratch ----------
__device__ __half g_xh [(size_t)M_TOT * K_TOT];
__device__ __half g_wh [(size_t)N_TOT * K_TOT];
__device__ __half g_ah [(size_t)RNK * K_TOT];
__device__ __half g_bh [(size_t)N_TOT * RNK];
__device__ __half g_xah[(size_t)M_TOT * RNK];
__device__ float  g_xp0[(size_t)M_TOT * RNK];
__device__ float  g_xp1[(size_t)M_TOT * RNK];

// ---------- helpers ----------
__device__ __forceinline__ uint32_t smem_u32(const void* p) {
    uint32_t a;
    asm("{ .reg .u64 t; cvta.to.shared.u64 t, %1; cvt.u32.u64 %0, t; }" : "=r"(a) : "l"(p));
    return a;
}
__device__ __forceinline__ void cp16(uint32_t s, const void* g) {
    asm volatile("cp.async.cg.shared.global [%0], [%1], 16;" :: "r"(s), "l"(g) : "memory");
}
__device__ __forceinline__ void ldsm4(uint32_t* r, uint32_t addr) {
    asm volatile("ldmatrix.sync.aligned.m8n8.x4.shared.b16 {%0,%1,%2,%3}, [%4];"
                 : "=r"(r[0]), "=r"(r[1]), "=r"(r[2]), "=r"(r[3]) : "r"(addr));
}
__device__ __forceinline__ void mma16(float* c, const uint32_t* a, uint32_t b0, uint32_t b1) {
    asm volatile(
        "mma.sync.aligned.m16n8k16.row.col.f32.f16.f16.f32 "
        "{%0,%1,%2,%3}, {%4,%5,%6,%7}, {%8,%9}, {%0,%1,%2,%3};"
        : "+f"(c[0]), "+f"(c[1]), "+f"(c[2]), "+f"(c[3])
        : "r"(a[0]), "r"(a[1]), "r"(a[2]), "r"(a[3]), "r"(b0), "r"(b1));
}
#define CP_COMMIT() asm volatile("cp.async.commit_group;" ::: "memory")
#define CP_WAIT0()  asm volatile("cp.async.wait_group 0;" ::: "memory")

// ---------- prepass: convert x, W, A, B to fp16 (RN) ----------
__global__ void round_all(const float2* __restrict__ x, const float2* __restrict__ W,
                          const float2* __restrict__ A, const float2* __restrict__ B)
{
    const int n_x = (M_TOT * K_TOT) / 2;
    const int n_w = (N_TOT * K_TOT) / 2;
    const int n_a = (RNK * K_TOT) / 2;
    const int n_b = (N_TOT * RNK) / 2;
    const int total = n_x + n_w + n_a + n_b;
    for (int i = blockIdx.x * blockDim.x + threadIdx.x; i < total; i += gridDim.x * blockDim.x) {
        const float2* src; __half2* dst; int j = i;
        if (j < n_x)               { src = x; dst = (__half2*)g_xh; }
        else if ((j -= n_x) < n_w) { src = W; dst = (__half2*)g_wh; }
        else if ((j -= n_w) < n_a) { src = A; dst = (__half2*)g_ah; }
        else                       { j -= n_a; src = B; dst = (__half2*)g_bh; }
        float2 v = src[j];
        dst[j] = __floats2half2_rn(v.x, v.y);
    }
}

// ---------- tile loader: one BK=128 chunk = 2 sub-tiles of A[BM] + B[BN] ----------
__device__ __forceinline__ void load_tiles(uint32_t sbase, const __half* pa, size_t lda,
                                           const __half* pb, size_t ldb, int tid)
{
    const int lrow = tid >> 3;
    const int lg   = tid & 7;
    const uint32_t sw = (uint32_t)(lg * 16) ^ (uint32_t)((lrow & 7) << 4);
    #pragma unroll
    for (int sub = 0; sub < 2; sub++) {
        const uint32_t sA = sbase + sub * A_SUB + lrow * 128 + sw;
        const __half* pat = pa + (size_t)lrow * lda + sub * 64 + lg * 8;
        #pragma unroll
        for (int i = 0; i < BM / 32; i++)
            cp16(sA + i * 32 * 128, pat + (size_t)i * 32 * lda);
    }
    #pragma unroll
    for (int sub = 0; sub < 2; sub++) {
        const uint32_t sB = sbase + 2 * A_SUB + sub * B_SUB + lrow * 128 + sw;
        const __half* pbt = pb + (size_t)lrow * ldb + sub * 64 + lg * 8;
        #pragma unroll
        for (int i = 0; i < 4; i++)
            cp16(sB + i * 32 * 128, pbt + (size_t)i * 32 * ldb);
    }
    CP_COMMIT();
}

// ---------- GEMM: C[256x128] = A[256,K] * B[128,K]^T  (fp16 in, f32 acc) ----------
template<bool MAIN>
__global__ __launch_bounds__(256, 1) void vera_gemm(
    const float* __restrict__ vec, float* __restrict__ outp, int nch)
{
    extern __shared__ char smem[];
    const uint32_t sb = smem_u32(smem);
    const int tid = threadIdx.x;
    const int wid = tid >> 5, lane = tid & 31;
    const int wm = wid >> 1, wn = wid & 1;

    const int nbx = gridDim.x;
    const int id = blockIdx.y * nbx + blockIdx.x;
    const int per_group = GROUP_M * nbx;
    const int grp = id / per_group;
    const int rem = id % per_group;
    const int m_block = (grp * GROUP_M + (rem % GROUP_M)) * BM;
    const int n_block = (rem / GROUP_M) * BN;
    const int k_base = blockIdx.z * nch * BK;

    float acc[4][8][4];
    #pragma unroll
    for (int i = 0; i < 4; i++)
        #pragma unroll
        for (int j = 0; j < 8; j++)
            #pragma unroll
            for (int k = 0; k < 4; k++) acc[i][j][k] = 0.0f;

    int rowA_off[4];
    #pragma unroll
    for (int mi = 0; mi < 4; mi++)
        rowA_off[mi] = (wm * 64 + mi * 16 + (lane & 15)) * 128;
    int rowB_off[4];
    #pragma unroll
    for (int njp = 0; njp < 4; njp++)
        rowB_off[njp] = (wn * 64 + njp * 16 + (lane & 15)) * 128;
    const uint32_t gsel = (uint32_t)(lane >> 4);
    const uint32_t xorS = (uint32_t)((lane & 7) << 4);
    uint32_t koff[4];
    #pragma unroll
    for (int ks = 0; ks < 4; ks++)
        koff[ks] = ((uint32_t)(ks * 32) + gsel * 16) ^ xorS;

    auto issue = [&](int kt) {
        const __half *pa, *pb; size_t lda, ldb;
        if (MAIN && kt >= K_TOT / BK) {
            const int kk = (kt - K_TOT / BK) * BK;
            pa = g_xah + (size_t)m_block * RNK + kk;  lda = RNK;
            pb = g_bh  + (size_t)n_block * RNK + kk;  ldb = RNK;
        } else {
            pa = g_xh + (size_t)m_block * K_TOT + k_base + kt * BK;  lda = K_TOT;
            pb = (MAIN ? g_wh : g_ah) + (size_t)n_block * K_TOT + k_base + kt * BK;  ldb = K_TOT;
        }
        load_tiles(sb + (kt & 1) * STAGE_BYTES, pa, lda, pb, ldb, tid);
    };

    issue(0);

    uint32_t af[2][4][4], bf[2][4][4];

    for (int kt = 0; kt < nch; kt++) {
        CP_WAIT0();          // chunk kt fully resident
        __syncthreads();     // all reads of stage (kt+1)&1 (chunk kt-1) done
        if (kt + 1 < nch) issue(kt + 1);

        const uint32_t stg = sb + (kt & 1) * STAGE_BYTES;

        // prime s=0 (sub 0)
        #pragma unroll
        for (int mi = 0; mi < 4; mi++) ldsm4(af[0][mi], stg + rowA_off[mi] + koff[0]);
        #pragma unroll
        for (int njp = 0; njp < 4; njp++)
            ldsm4(bf[0][njp], stg + 2 * A_SUB + rowB_off[njp] + koff[0]);

        #pragma unroll
        for (int s = 0; s < 8; s++) {          // 8 x k16 per chunk
            const int cur = s & 1, nxt = cur ^ 1;
            if (s < 7) {
                const int sn = s + 1;
                const uint32_t aA = stg + (sn >> 2) * A_SUB;
                const uint32_t aB = stg + 2 * A_SUB + (sn >> 2) * B_SUB;
                const uint32_t ko = koff[sn & 3];
                #pragma unroll
                for (int mi = 0; mi < 4; mi++) ldsm4(af[nxt][mi], aA + rowA_off[mi] + ko);
                #pragma unroll
                for (int njp = 0; njp < 4; njp++) ldsm4(bf[nxt][njp], aB + rowB_off[njp] + ko);
            }
            #pragma unroll
            for (int mi = 0; mi < 4; mi++)
                #pragma unroll
                for (int njp = 0; njp < 4; njp++) {
                    mma16(acc[mi][njp * 2 + 0], af[cur][mi], bf[cur][njp][0], bf[cur][njp][2]);
                    mma16(acc[mi][njp * 2 + 1], af[cur][mi], bf[cur][njp][1], bf[cur][njp][3]);
                }
        }
    }

    // epilogue: acc[mi][njp*2+p] -> n = wn*64 + njp*16 + p*8 + lc*2
    const int lr = lane >> 2, lc = lane & 3;
    float* pdst = MAIN ? outp : (blockIdx.z ? g_xp1 : g_xp0);
    #pragma unroll
    for (int mi = 0; mi < 4; mi++) {
        #pragma unroll
        for (int nj = 0; nj < 8; nj++) {
            const int m = m_block + wm * 64 + mi * 16 + lr;
            const int n = n_block + wn * 64 + (nj >> 1) * 16 + (nj & 1) * 8 + lc * 2;
            if (MAIN) {
                const float b0 = __ldg(&vec[n]), b1 = __ldg(&vec[n + 1]);
                *(float2*)&pdst[(size_t)m * N_TOT + n] =
                    make_float2(acc[mi][nj][0] + b0, acc[mi][nj][1] + b1);
                *(float2*)&pdst[(size_t)(m + 8) * N_TOT + n] =
                    make_float2(acc[mi][nj][2] + b0, acc[mi][nj][3] + b1);
            } else {
                *(float2*)&pdst[(size_t)m * RNK + n] =
                    make_float2(acc[mi][nj][0], acc[mi][nj][1]);
                *(float2*)&pdst[(size_t)(m + 8) * RNK + n] =
                    make_float2(acc[mi][nj][2], acc[mi][nj][3]);
            }
        }
    }
}

// ---------- combine: xa = fp16((p0 + p1) * d) ----------
__global__ void xa_combine(const float* __restrict__ dvec) {
    const int n4 = (M_TOT * RNK) / 4;
    for (int i = blockIdx.x * blockDim.x + threadIdx.x; i < n4; i += gridDim.x * blockDim.x) {
        float4 p0 = ((const float4*)g_xp0)[i];
        float4 p1 = ((const float4*)g_xp1)[i];
        const int n = (i * 4) & (RNK - 1);
        __half2 h0 = __floats2half2_rn((p0.x + p1.x) * __ldg(&dvec[n + 0]),
                                       (p0.y + p1.y) * __ldg(&dvec[n + 1]));
        __half2 h1 = __floats2half2_rn((p0.z + p1.z) * __ldg(&dvec[n + 2]),
                                       (p0.w + p1.w) * __ldg(&dvec[n + 3]));
        ((__half2*)g_xah)[i * 2 + 0] = h0;
        ((__half2*)g_xah)[i * 2 + 1] = h1;
    }
}

// ---------- launch ----------
extern "C" void kernel_launch(void* const* d_in, const int* in_sizes, int n_in,
                              void* d_out, int out_size)
{
    const float* x    = (const float*)d_in[0];
    const float* W    = (const float*)d_in[1];
    const float* Amat = (const float*)d_in[2];
    const float* Bmat = (const float*)d_in[3];
    const float* dvec = (const float*)d_in[4];
    const float* bias = (const float*)d_in[5];
    float* out = (float*)d_out;
    (void)Amat; (void)Bmat; (void)W; (void)x;

    cudaFuncSetAttribute(vera_gemm<true>,  cudaFuncAttributeMaxDynamicSharedMemorySize, SMEM_TOTAL);
    cudaFuncSetAttribute(vera_gemm<false>, cudaFuncAttributeMaxDynamicSharedMemorySize, SMEM_TOTAL);

    round_all<<<3552, 256>>>((const float2*)x, (const float2*)W,
                             (const float2*)Amat, (const float2*)Bmat);

    // xa partials: split-K x2, BM=256 -> 2 x 32 x 2 = 128 CTAs, 16 chunks each
    vera_gemm<false><<<dim3(RNK / BN, M_TOT / BM, 2), 256, SMEM_TOTAL>>>(
        nullptr, nullptr, (K_TOT / 2) / BK);
    xa_combine<<<2048, 256>>>(dvec);

    // y = x @ W^T + xa @ B^T + b   (32 + 2 chunks)
    vera_gemm<true><<<dim3(N_TOT / BN, M_TOT / BM, 1), 256, SMEM_TOTAL>>>(
        bias, out, K_TOT / BK + RNK / BK);
}

// round 13
// speedup vs baseline: 1.1257x; 1.1257x over previous
#include <cuda_runtime.h>
#include <cuda_fp16.h>
#include <cstdint>
#include <cstddef>

// VeRA: y = x @ W^T + ((x @ A^T) * d) @ B^T + b    (all f32 I/O)
// fp16 mma.sync m16n8k16 (f32 acc), BK=64, 4-stage cp.async, cross-chunk
// register fragment pipeline. xa via split-K x2 (BM=256) + combine.

#define M_TOT 8192
#define N_TOT 4096
#define K_TOT 4096
#define RNK   256

#define BN 128
#define BK 64                 // halves per chunk = 128 bytes/row
#define STAGES 4
#define GROUP_M 8

// ---------- static scratch ----------
__device__ __half g_xh [(size_t)M_TOT * K_TOT];   // 64 MB
__device__ __half g_wh [(size_t)N_TOT * K_TOT];   // 32 MB
__device__ __half g_ah [(size_t)RNK * K_TOT];     //  2 MB
__device__ __half g_bh [(size_t)N_TOT * RNK];     //  2 MB
__device__ __half g_xah[(size_t)M_TOT * RNK];     //  4 MB  xa = (x@A^T)*d
__device__ float  g_xp0[(size_t)M_TOT * RNK];     // split-K partial 0
__device__ float  g_xp1[(size_t)M_TOT * RNK];     // split-K partial 1

// ---------- helpers ----------
__device__ __forceinline__ uint32_t smem_u32(const void* p) {
    uint32_t a;
    asm("{ .reg .u64 t; cvta.to.shared.u64 t, %1; cvt.u32.u64 %0, t; }" : "=r"(a) : "l"(p));
    return a;
}
__device__ __forceinline__ void cp16(uint32_t s, const void* g) {
    asm volatile("cp.async.cg.shared.global [%0], [%1], 16;" :: "r"(s), "l"(g) : "memory");
}
__device__ __forceinline__ void ldsm4(uint32_t* r, uint32_t addr) {
    asm volatile("ldmatrix.sync.aligned.m8n8.x4.shared.b16 {%0,%1,%2,%3}, [%4];"
                 : "=r"(r[0]), "=r"(r[1]), "=r"(r[2]), "=r"(r[3]) : "r"(addr));
}
__device__ __forceinline__ void mma16(float* c, const uint32_t* a, uint32_t b0, uint32_t b1) {
    asm volatile(
        "mma.sync.aligned.m16n8k16.row.col.f32.f16.f16.f32 "
        "{%0,%1,%2,%3}, {%4,%5,%6,%7}, {%8,%9}, {%0,%1,%2,%3};"
        : "+f"(c[0]), "+f"(c[1]), "+f"(c[2]), "+f"(c[3])
        : "r"(a[0]), "r"(a[1]), "r"(a[2]), "r"(a[3]), "r"(b0), "r"(b1));
}
#define CP_COMMIT() asm volatile("cp.async.commit_group;" ::: "memory")
#define CP_WAIT(n)  asm volatile("cp.async.wait_group %0;" :: "n"(n) : "memory")

// ---------- prepass: convert x, W, A, B to fp16 (RN) in one launch ----------
__global__ void round_all(const float2* __restrict__ x, const float2* __restrict__ W,
                          const float2* __restrict__ A, const float2* __restrict__ B)
{
    const int n_x = (M_TOT * K_TOT) / 2;
    const int n_w = (N_TOT * K_TOT) / 2;
    const int n_a = (RNK * K_TOT) / 2;
    const int n_b = (N_TOT * RNK) / 2;
    const int total = n_x + n_w + n_a + n_b;
    for (int i = blockIdx.x * blockDim.x + threadIdx.x; i < total; i += gridDim.x * blockDim.x) {
        const float2* src; __half2* dst; int j = i;
        if (j < n_x)               { src = x; dst = (__half2*)g_xh; }
        else if ((j -= n_x) < n_w) { src = W; dst = (__half2*)g_wh; }
        else if ((j -= n_w) < n_a) { src = A; dst = (__half2*)g_ah; }
        else                       { j -= n_a; src = B; dst = (__half2*)g_bh; }
        float2 v = src[j];
        dst[j] = __floats2half2_rn(v.x, v.y);
    }
}

// ---------- tile loader: A[BM rows] + B[BN rows], 128B per row ----------
template<int BM>
__device__ __forceinline__ void load_tiles(uint32_t sbase, const __half* pa, size_t lda,
                                           const __half* pb, size_t ldb, int tid)
{
    const int lrow = tid >> 3;
    const int lg   = tid & 7;
    const uint32_t sw = (uint32_t)(lg * 16) ^ (uint32_t)((lrow & 7) << 4);
    const uint32_t sA = sbase + lrow * 128 + sw;
    const uint32_t sB = sbase + BM * 128 + lrow * 128 + sw;
    const __half* pat = pa + (size_t)lrow * lda + lg * 8;
    const __half* pbt = pb + (size_t)lrow * ldb + lg * 8;
    #pragma unroll
    for (int i = 0; i < BM / 32; i++)
        cp16(sA + i * 32 * 128, pat + (size_t)i * 32 * lda);
    #pragma unroll
    for (int i = 0; i < 4; i++)
        cp16(sB + i * 32 * 128, pbt + (size_t)i * 32 * ldb);
    CP_COMMIT();
}

// ---------- GEMM: C[BM x 128] = A[BM,K] * B[128,K]^T  (fp16 in, f32 acc) ----------
// MAIN: A=g_xh, B=g_wh (64 chunks) then tail g_xah/g_bh (4 chunks); +bias -> outp.
// !MAIN: A=g_xh, B=g_ah, K-slice by blockIdx.z; raw partials -> g_xp{0,1}.
template<bool MAIN, int MI>
__global__ __launch_bounds__(256, 1) void vera_gemm(
    const float* __restrict__ vec, float* __restrict__ outp, int nch)
{
    constexpr int BM = MI * 64;
    constexpr int A_BYTES = BM * 128;
    constexpr int STAGE_BYTES = (BM + BN) * 128;

    extern __shared__ char smem[];
    const uint32_t sb = smem_u32(smem);
    const int tid = threadIdx.x;
    const int wid = tid >> 5, lane = tid & 31;
    const int wm = wid >> 1, wn = wid & 1;

    const int nbx = gridDim.x;
    const int id = blockIdx.y * nbx + blockIdx.x;
    const int per_group = GROUP_M * nbx;
    const int grp = id / per_group;
    const int rem = id % per_group;
    const int m_block = (grp * GROUP_M + (rem % GROUP_M)) * BM;
    const int n_block = (rem / GROUP_M) * BN;
    const int k_base = blockIdx.z * nch * BK;   // split-K offset (halves)

    float acc[MI][8][4];
    #pragma unroll
    for (int i = 0; i < MI; i++)
        #pragma unroll
        for (int j = 0; j < 8; j++)
            #pragma unroll
            for (int k = 0; k < 4; k++) acc[i][j][k] = 0.0f;

    int rowA_off[MI];
    #pragma unroll
    for (int mi = 0; mi < MI; mi++)
        rowA_off[mi] = (wm * (MI * 16) + mi * 16 + (lane & 15)) * 128;
    int rowB_off[4];
    #pragma unroll
    for (int njp = 0; njp < 4; njp++)
        rowB_off[njp] = (wn * 64 + njp * 16 + (lane & 15)) * 128;
    const uint32_t gsel = (uint32_t)(lane >> 4);        // 0/1 -> k halves (+16B)
    const uint32_t xorS = (uint32_t)((lane & 7) << 4);  // swizzle

    auto chunk_ptrs = [&](int kt, const __half*& pa, size_t& lda, const __half*& pb, size_t& ldb) {
        if (MAIN && kt >= K_TOT / BK) {
            const int kk = (kt - K_TOT / BK) * BK;
            pa = g_xah + (size_t)m_block * RNK + kk;  lda = RNK;
            pb = g_bh  + (size_t)n_block * RNK + kk;  ldb = RNK;
        } else {
            pa = g_xh + (size_t)m_block * K_TOT + k_base + kt * BK;  lda = K_TOT;
            pb = (MAIN ? g_wh : g_ah) + (size_t)n_block * K_TOT + k_base + kt * BK;  ldb = K_TOT;
        }
    };
    auto issue = [&](int kt) {
        const __half *pa, *pb; size_t lda, ldb;
        chunk_ptrs(kt, pa, lda, pb, ldb);
        load_tiles<BM>(sb + (kt % STAGES) * STAGE_BYTES, pa, lda, pb, ldb, tid);
    };

    #pragma unroll
    for (int s = 0; s < STAGES - 1; s++) issue(s);

    uint32_t af[2][MI][4], bf[2][4][4];

    CP_WAIT(2);
    __syncthreads();
    {
        const uint32_t sA = sb, sB = sb + A_BYTES;
        const uint32_t koff = (gsel * 16) ^ xorS;
        #pragma unroll
        for (int mi = 0; mi < MI; mi++) ldsm4(af[0][mi], sA + rowA_off[mi] + koff);
        #pragma unroll
        for (int njp = 0; njp < 4; njp++) ldsm4(bf[0][njp], sB + rowB_off[njp] + koff);
    }

    for (int kt = 0; kt < nch; kt++) {
        CP_WAIT(1);          // chunks kt and kt+1 resident
        __syncthreads();     // releases stage (kt-1)%STAGES
        if (kt + STAGES - 1 < nch) issue(kt + STAGES - 1);
        else CP_COMMIT();

        const uint32_t sA = sb + (kt % STAGES) * STAGE_BYTES;
        const uint32_t sB = sA + A_BYTES;
        const uint32_t sA1 = sb + ((kt + 1) % STAGES) * STAGE_BYTES;
        const uint32_t sB1 = sA1 + A_BYTES;

        #pragma unroll
        for (int s = 0; s < 4; s++) {          // 4 x k16 per 128B chunk
            const int cur = s & 1, nxt = cur ^ 1;
            if (s < 3) {
                const uint32_t koff = ((uint32_t)((s + 1) * 32) + gsel * 16) ^ xorS;
                #pragma unroll
                for (int mi = 0; mi < MI; mi++) ldsm4(af[nxt][mi], sA + rowA_off[mi] + koff);
                #pragma unroll
                for (int njp = 0; njp < 4; njp++) ldsm4(bf[nxt][njp], sB + rowB_off[njp] + koff);
            } else if (kt + 1 < nch) {
                const uint32_t koff = (gsel * 16) ^ xorS;
                #pragma unroll
                for (int mi = 0; mi < MI; mi++) ldsm4(af[nxt][mi], sA1 + rowA_off[mi] + koff);
                #pragma unroll
                for (int njp = 0; njp < 4; njp++) ldsm4(bf[nxt][njp], sB1 + rowB_off[njp] + koff);
            }
            #pragma unroll
            for (int mi = 0; mi < MI; mi++)
                #pragma unroll
                for (int njp = 0; njp < 4; njp++) {
                    mma16(acc[mi][njp * 2 + 0], af[cur][mi], bf[cur][njp][0], bf[cur][njp][2]);
                    mma16(acc[mi][njp * 2 + 1], af[cur][mi], bf[cur][njp][1], bf[cur][njp][3]);
                }
        }
    }

    // epilogue: acc[mi][njp*2+p] covers n = wn*64 + njp*16 + p*8 + lc*2
    const int lr = lane >> 2, lc = lane & 3;
    float* pdst = MAIN ? outp : (blockIdx.z ? g_xp1 : g_xp0);
    #pragma unroll
    for (int mi = 0; mi < MI; mi++) {
        #pragma unroll
        for (int nj = 0; nj < 8; nj++) {
            const int m = m_block + wm * (MI * 16) + mi * 16 + lr;
            const int n = n_block + wn * 64 + (nj >> 1) * 16 + (nj & 1) * 8 + lc * 2;
            if (MAIN) {
                const float b0 = __ldg(&vec[n]), b1 = __ldg(&vec[n + 1]);
                *(float2*)&pdst[(size_t)m * N_TOT + n] =
                    make_float2(acc[mi][nj][0] + b0, acc[mi][nj][1] + b1);
                *(float2*)&pdst[(size_t)(m + 8) * N_TOT + n] =
                    make_float2(acc[mi][nj][2] + b0, acc[mi][nj][3] + b1);
            } else {
                *(float2*)&pdst[(size_t)m * RNK + n] =
                    make_float2(acc[mi][nj][0], acc[mi][nj][1]);
                *(float2*)&pdst[(size_t)(m + 8) * RNK + n] =
                    make_float2(acc[mi][nj][2], acc[mi][nj][3]);
            }
        }
    }
}

// ---------- combine: xa = fp16((p0 + p1) * d) ----------
__global__ void xa_combine(const float* __restrict__ dvec) {
    const int n4 = (M_TOT * RNK) / 4;
    for (int i = blockIdx.x * blockDim.x + threadIdx.x; i < n4; i += gridDim.x * blockDim.x) {
        float4 p0 = ((const float4*)g_xp0)[i];
        float4 p1 = ((const float4*)g_xp1)[i];
        const int n = (i * 4) & (RNK - 1);
        __half2 h0 = __floats2half2_rn((p0.x + p1.x) * __ldg(&dvec[n + 0]),
                                       (p0.y + p1.y) * __ldg(&dvec[n + 1]));
        __half2 h1 = __floats2half2_rn((p0.z + p1.z) * __ldg(&dvec[n + 2]),
                                       (p0.w + p1.w) * __ldg(&dvec[n + 3]));
        ((__half2*)g_xah)[i * 2 + 0] = h0;
        ((__half2*)g_xah)[i * 2 + 1] = h1;
    }
}

// ---------- launch ----------
extern "C" void kernel_launch(void* const* d_in, const int* in_sizes, int n_in,
                              void* d_out, int out_size)
{
    const float* x    = (const float*)d_in[0];
    const float* W    = (const float*)d_in[1];
    const float* Amat = (const float*)d_in[2];
    const float* Bmat = (const float*)d_in[3];
    const float* dvec = (const float*)d_in[4];
    const float* bias = (const float*)d_in[5];
    float* out = (float*)d_out;

    constexpr int MAIN_SMEM = STAGES * (256 + BN) * 128;   // 196608
    cudaFuncSetAttribute(vera_gemm<true, 4>,  cudaFuncAttributeMaxDynamicSharedMemorySize, MAIN_SMEM);
    cudaFuncSetAttribute(vera_gemm<false, 4>, cudaFuncAttributeMaxDynamicSharedMemorySize, MAIN_SMEM);

    // convert inputs to fp16
    round_all<<<3552, 256>>>((const float2*)x, (const float2*)W,
                             (const float2*)Amat, (const float2*)Bmat);

    // xa partials: split-K x2, BM=256 -> (2 n-blocks x 32 m-blocks x 2 splits) = 128 CTAs
    vera_gemm<false, 4><<<dim3(RNK / BN, M_TOT / 256, 2), 256, MAIN_SMEM>>>(
        nullptr, nullptr, (K_TOT / 2) / BK);
    xa_combine<<<2048, 256>>>(dvec);

    // y = x @ W^T + xa @ B^T + b   (64 + 4 chunks)
    vera_gemm<true, 4><<<dim3(N_TOT / BN, M_TOT / 256, 1), 256, MAIN_SMEM>>>(
        bias, out, K_TOT / BK + RNK / BK);
}